// round 7
// baseline (speedup 1.0000x reference)
#include <cuda_runtime.h>

#define N_NODES_MAX 100096
#define N_EDGES_MAX 3200256
#define N_FEAT 128
#define EMBED 20
#define N_GRAPHS 64
#define N_CLASSES 10

// Scratch (device globals; no dynamic allocation allowed)
__device__ __align__(128) float g_xw[N_NODES_MAX * EMBED];     // x @ W
__device__ __align__(128) float g_emb[N_NODES_MAX * EMBED];    // post-norm/relu embeddings
__device__ __align__(128) float g_deg[N_NODES_MAX];
__device__ __align__(128) float g_dinv[N_NODES_MAX];
__device__ __align__(128) int   g_cnt[N_NODES_MAX];            // in-degree (real edges)
__device__ __align__(128) int   g_start[N_NODES_MAX];          // CSR offsets
__device__ __align__(128) int   g_fill[N_NODES_MAX];           // scatter cursors
__device__ __align__(128) int   g_total;                       // running offset
__device__ __align__(128) int   g_esrc[N_EDGES_MAX];           // CSR: source node
__device__ __align__(128) float g_enorm[N_EDGES_MAX];          // CSR: edge norm
__device__ __align__(128) float g_gmax[N_GRAPHS * EMBED];
__device__ __align__(128) float g_gsum[N_GRAPHS * EMBED];
__device__ __align__(128) float g_gcnt[N_GRAPHS];
__device__ int g_ei64;     // 1 if edge_index is int64, 0 if int32
__device__ int g_batch64;  // 1 if batch is int64, 0 if int32

// Index load that works for either dtype, clamped to [0, limit-1].
__device__ __forceinline__ int load_idx(const void* p, size_t i, int is64, int limit) {
    long long v = is64 ? ((const long long*)p)[i] : (long long)((const int*)p)[i];
    int iv = (int)v;
    if (iv < 0) iv = 0;
    if (iv >= limit) iv = limit - 1;
    return iv;
}

// ---------------------------------------------------------------------------
// Probe dtypes: for int64 data with small nonneg values, every odd 32-bit
// word is 0. Sample regions where genuine int32 values are nonzero.
// ---------------------------------------------------------------------------
__global__ void k_probe(const unsigned int* ei, const unsigned int* batch, int n) {
    int bad_ei = 0, bad_b = 0;
    // edge_index: words [0, 2048) are in-bounds for both dtypes.
    for (int i = threadIdx.x; i < 1024; i += 256)
        if (ei[2 * i + 1] != 0u) bad_ei = 1;
    // batch: sample around n/4 (batch values ~16 there, nonzero if int32).
    int base = n / 4;
    for (int i = threadIdx.x; i < 1024; i += 256)
        if (batch[2 * (base + i) + 1] != 0u) bad_b = 1;
    int any_ei = __syncthreads_or(bad_ei);
    int any_b  = __syncthreads_or(bad_b);
    if (threadIdx.x == 0) {
        g_ei64 = any_ei ? 0 : 1;     // all-zero odd words => int64
        g_batch64 = any_b ? 0 : 1;
    }
}

// ---------------------------------------------------------------------------
// Init: deg = 1 (self-loop weight), counters zeroed every call
// ---------------------------------------------------------------------------
__global__ void k_init(int n) {
    int i = blockIdx.x * blockDim.x + threadIdx.x;
    if (i < n) { g_deg[i] = 1.0f; g_cnt[i] = 0; g_fill[i] = 0; }
    if (i == 0) g_total = 0;
}

// ---------------------------------------------------------------------------
// xw = x @ W.  One thread per node, 20 accumulators, W staged in smem.
// ---------------------------------------------------------------------------
__global__ __launch_bounds__(256) void k_xw(const float* __restrict__ x,
                                            const float* __restrict__ W, int n) {
    __shared__ float Ws[N_FEAT * EMBED];
    for (int i = threadIdx.x; i < N_FEAT * EMBED; i += 256) Ws[i] = W[i];
    __syncthreads();
    int node = blockIdx.x * 256 + threadIdx.x;
    if (node >= n) return;
    float acc[EMBED];
#pragma unroll
    for (int j = 0; j < EMBED; j++) acc[j] = 0.0f;
    const float4* xr = (const float4*)(x + (size_t)node * N_FEAT);
#pragma unroll 8
    for (int k4 = 0; k4 < N_FEAT / 4; k4++) {
        float4 v = __ldg(&xr[k4]);
        const float* Wr = &Ws[(k4 * 4) * EMBED];
#pragma unroll
        for (int j = 0; j < EMBED; j++) {
            float a = acc[j];
            a = fmaf(v.x, Wr[j], a);
            a = fmaf(v.y, Wr[EMBED + j], a);
            a = fmaf(v.z, Wr[2 * EMBED + j], a);
            a = fmaf(v.w, Wr[3 * EMBED + j], a);
            acc[j] = a;
        }
    }
    float4* o = (float4*)&g_xw[node * EMBED];
#pragma unroll
    for (int q = 0; q < 5; q++) {
        float4 v;
        v.x = acc[q * 4 + 0]; v.y = acc[q * 4 + 1];
        v.z = acc[q * 4 + 2]; v.w = acc[q * 4 + 3];
        o[q] = v;
    }
}

// ---------------------------------------------------------------------------
// deg[dst] += w ; cnt[dst] += 1   (spread atomics, L2-resident tables)
// ---------------------------------------------------------------------------
__global__ void k_deg(const void* __restrict__ ei,
                      const float* __restrict__ w, int E, int n) {
    int e = blockIdx.x * blockDim.x + threadIdx.x;
    if (e >= E) return;
    int is64 = g_ei64;
    int d = load_idx(ei, (size_t)E + e, is64, n);
    atomicAdd(&g_deg[d], w[e]);
    atomicAdd(&g_cnt[d], 1);
}

// ---------------------------------------------------------------------------
// dinv = rsqrt(deg); CSR offsets via warp-aggregated scan
// ---------------------------------------------------------------------------
__global__ void k_start(int n) {
    int i = blockIdx.x * blockDim.x + threadIdx.x;
    int lane = threadIdx.x & 31;
    int c = (i < n) ? g_cnt[i] : 0;
    if (i < n) {
        float d = g_deg[i];
        g_dinv[i] = (d > 0.0f) ? rsqrtf(d) : 0.0f;
    }
    int pre = c;
#pragma unroll
    for (int o = 1; o < 32; o <<= 1) {
        int v = __shfl_up_sync(0xffffffffu, pre, o);
        if (lane >= o) pre += v;
    }
    int warp_tot = __shfl_sync(0xffffffffu, pre, 31);
    int base = 0;
    if (lane == 31) base = atomicAdd(&g_total, warp_tot);
    base = __shfl_sync(0xffffffffu, base, 31);
    if (i < n) g_start[i] = base + (pre - c);
}

// ---------------------------------------------------------------------------
// Bin edges by dst: store (src, norm) at a claimed CSR slot
// ---------------------------------------------------------------------------
__global__ void k_scatter(const void* __restrict__ ei,
                          const float* __restrict__ w, int E, int n) {
    int e = blockIdx.x * blockDim.x + threadIdx.x;
    if (e >= E) return;
    int is64 = g_ei64;
    int s = load_idx(ei, e, is64, n);
    int d = load_idx(ei, (size_t)E + e, is64, n);
    float nm = g_dinv[s] * w[e] * g_dinv[d];
    int pos = g_start[d] + atomicAdd(&g_fill[d], 1);
    if (pos < 0) pos = 0;
    if (pos >= N_EDGES_MAX) pos = N_EDGES_MAX - 1;
    g_esrc[pos] = s;
    g_enorm[pos] = nm;
}

// ---------------------------------------------------------------------------
// Gather per node (self-loop + CSR in-edges), fused +b / L2-normalize / ReLU.
// ---------------------------------------------------------------------------
__global__ __launch_bounds__(256) void k_gather(const float* __restrict__ b, int n) {
    int i = blockIdx.x * 256 + threadIdx.x;
    if (i >= n) return;
    float acc[EMBED];
    {
        float di = g_dinv[i];
        float s2 = di * di;
        const float4* p = (const float4*)&g_xw[i * EMBED];
#pragma unroll
        for (int q = 0; q < 5; q++) {
            float4 v = p[q];
            acc[q * 4 + 0] = v.x * s2; acc[q * 4 + 1] = v.y * s2;
            acc[q * 4 + 2] = v.z * s2; acc[q * 4 + 3] = v.w * s2;
        }
    }
    int st = g_start[i];
    int c  = g_cnt[i];
    for (int k = 0; k < c; k++) {
        int s = g_esrc[st + k];
        float nm = g_enorm[st + k];
        const float4* p = (const float4*)&g_xw[s * EMBED];
#pragma unroll
        for (int q = 0; q < 5; q++) {
            float4 v = p[q];
            acc[q * 4 + 0] = fmaf(v.x, nm, acc[q * 4 + 0]);
            acc[q * 4 + 1] = fmaf(v.y, nm, acc[q * 4 + 1]);
            acc[q * 4 + 2] = fmaf(v.z, nm, acc[q * 4 + 2]);
            acc[q * 4 + 3] = fmaf(v.w, nm, acc[q * 4 + 3]);
        }
    }
    float ss = 0.0f;
#pragma unroll
    for (int j = 0; j < EMBED; j++) {
        acc[j] += b[j];
        ss = fmaf(acc[j], acc[j], ss);
    }
    float inv = 1.0f / fmaxf(sqrtf(ss), 1e-12f);
    float4* o = (float4*)&g_emb[i * EMBED];
#pragma unroll
    for (int q = 0; q < 5; q++) {
        float4 v;
        v.x = fmaxf(acc[q * 4 + 0] * inv, 0.0f);
        v.y = fmaxf(acc[q * 4 + 1] * inv, 0.0f);
        v.z = fmaxf(acc[q * 4 + 2] * inv, 0.0f);
        v.w = fmaxf(acc[q * 4 + 3] * inv, 0.0f);
        o[q] = v;
    }
}

// ---------------------------------------------------------------------------
// Pooling: one block per graph (batch sorted -> binary-search node range).
// Pure shfl/shared tree reductions; exclusive writes; NO atomics.
// ---------------------------------------------------------------------------
__device__ __forceinline__ long long load_b(const void* p, int i, int is64) {
    return is64 ? ((const long long*)p)[i] : (long long)((const int*)p)[i];
}

__global__ __launch_bounds__(256) void k_pool(const void* __restrict__ batch, int n) {
    int g = blockIdx.x;
    int is64 = g_batch64;
    int lo = 0, hi = n;
    while (lo < hi) { int m = (lo + hi) >> 1; if (load_b(batch, m, is64) < (long long)g) lo = m + 1; else hi = m; }
    int beg = lo;
    lo = beg; hi = n;
    while (lo < hi) { int m = (lo + hi) >> 1; if (load_b(batch, m, is64) < (long long)(g + 1)) lo = m + 1; else hi = m; }
    int end = lo;

    float mx[EMBED], sm[EMBED];
#pragma unroll
    for (int j = 0; j < EMBED; j++) { mx[j] = 0.0f; sm[j] = 0.0f; }
    int cnt = 0;
    for (int i = beg + threadIdx.x; i < end; i += 256) {
        const float4* p = (const float4*)&g_emb[i * EMBED];
#pragma unroll
        for (int q = 0; q < 5; q++) {
            float4 v = p[q];
            mx[q * 4 + 0] = fmaxf(mx[q * 4 + 0], v.x); sm[q * 4 + 0] += v.x;
            mx[q * 4 + 1] = fmaxf(mx[q * 4 + 1], v.y); sm[q * 4 + 1] += v.y;
            mx[q * 4 + 2] = fmaxf(mx[q * 4 + 2], v.z); sm[q * 4 + 2] += v.z;
            mx[q * 4 + 3] = fmaxf(mx[q * 4 + 3], v.w); sm[q * 4 + 3] += v.w;
        }
        cnt++;
    }
#pragma unroll
    for (int o = 16; o > 0; o >>= 1) {
#pragma unroll
        for (int j = 0; j < EMBED; j++) {
            mx[j] = fmaxf(mx[j], __shfl_down_sync(0xffffffffu, mx[j], o));
            sm[j] += __shfl_down_sync(0xffffffffu, sm[j], o);
        }
        cnt += __shfl_down_sync(0xffffffffu, cnt, o);
    }
    __shared__ float wmx[8][EMBED];
    __shared__ float wsm[8][EMBED];
    __shared__ int   wcnt[8];
    int wid = threadIdx.x >> 5, lane = threadIdx.x & 31;
    if (lane == 0) {
#pragma unroll
        for (int j = 0; j < EMBED; j++) { wmx[wid][j] = mx[j]; wsm[wid][j] = sm[j]; }
        wcnt[wid] = cnt;
    }
    __syncthreads();
    if (threadIdx.x < EMBED) {
        int j = threadIdx.x;
        float m = wmx[0][j], s = wsm[0][j];
#pragma unroll
        for (int wv = 1; wv < 8; wv++) { m = fmaxf(m, wmx[wv][j]); s += wsm[wv][j]; }
        g_gmax[g * EMBED + j] = m;
        g_gsum[g * EMBED + j] = s;
    }
    if (threadIdx.x == 32) {
        int c = wcnt[0];
#pragma unroll
        for (int wv = 1; wv < 8; wv++) c += wcnt[wv];
        g_gcnt[g] = (float)c;
    }
}

// ---------------------------------------------------------------------------
// Final: pooled[g] = [max, sum/cnt] ; out = pooled @ lin_W + lin_b
// ---------------------------------------------------------------------------
__global__ void k_final(const float* __restrict__ linW,
                        const float* __restrict__ linb, float* __restrict__ out) {
    int t = blockIdx.x * blockDim.x + threadIdx.x;
    if (t >= N_GRAPHS * N_CLASSES) return;
    int g = t / N_CLASSES, c = t % N_CLASSES;
    float inv = 1.0f / fmaxf(g_gcnt[g], 1.0f);
    float acc = linb[c];
#pragma unroll
    for (int k = 0; k < EMBED; k++)
        acc = fmaf(g_gmax[g * EMBED + k], linW[k * N_CLASSES + c], acc);
#pragma unroll
    for (int k = 0; k < EMBED; k++)
        acc = fmaf(g_gsum[g * EMBED + k] * inv, linW[(EMBED + k) * N_CLASSES + c], acc);
    out[g * N_CLASSES + c] = acc;
}

// ---------------------------------------------------------------------------
extern "C" void kernel_launch(void* const* d_in, const int* in_sizes, int n_in,
                              void* d_out, int out_size) {
    // Identify inputs by element count (all sizes distinct); positional fallback.
    const float* x = 0; const void* ei = 0; const float* w = 0; const void* batch = 0;
    const float* W = 0; const float* b = 0; const float* linW = 0; const float* linb = 0;
    for (int i = 0; i < n_in; i++) {
        switch (in_sizes[i]) {
            case 12800000: x     = (const float*)d_in[i]; break;  // 100000*128
            case 6400000:  ei    = d_in[i];               break;  // 2*3200000
            case 3200000:  w     = (const float*)d_in[i]; break;
            case 100000:   batch = d_in[i];               break;
            case 2560:     W     = (const float*)d_in[i]; break;  // 128*20
            case 400:      linW  = (const float*)d_in[i]; break;  // 40*10
            case 20:       b     = (const float*)d_in[i]; break;
            case 10:       linb  = (const float*)d_in[i]; break;
            default: break;
        }
    }
    if (!x || !ei || !w || !batch || !W || !b || !linW || !linb) {
        x = (const float*)d_in[0]; ei = d_in[1]; w = (const float*)d_in[2];
        batch = d_in[3]; W = (const float*)d_in[4]; b = (const float*)d_in[5];
        linW = (const float*)d_in[6]; linb = (const float*)d_in[7];
    }
    int n = 100000, E = 3200000;
    for (int i = 0; i < n_in; i++) {
        if (d_in[i] == (const void*)batch) n = in_sizes[i];
        if (d_in[i] == ei) E = in_sizes[i] / 2;
    }

    k_probe<<<1, 256>>>((const unsigned int*)ei, (const unsigned int*)batch, n);
    k_init<<<(n + 255) / 256, 256>>>(n);
    k_xw<<<(n + 255) / 256, 256>>>(x, W, n);
    k_deg<<<(E + 255) / 256, 256>>>(ei, w, E, n);
    k_start<<<(n + 255) / 256, 256>>>(n);
    k_scatter<<<(E + 255) / 256, 256>>>(ei, w, E, n);
    k_gather<<<(n + 255) / 256, 256>>>(b, n);
    k_pool<<<N_GRAPHS, 256>>>(batch, n);
    k_final<<<(N_GRAPHS * N_CLASSES + 255) / 256, 256>>>(linW, linb, (float*)d_out);
}

// round 8
// speedup vs baseline: 1.3397x; 1.3397x over previous
#include <cuda_runtime.h>
#include <cuda_fp16.h>

#define N_NODES_MAX 100096
#define N_EDGES_MAX 3200256
#define N_FEAT 128
#define EMBED 20
#define N_GRAPHS 64
#define N_CLASSES 10
#define YROW 16  // uints per y-row (64B: 20 halfs used, padded to 32)

// Scratch (device globals; no dynamic allocation allowed)
__device__ __align__(128) float g_xw[N_NODES_MAX * EMBED];        // x @ W (fp32, self term)
__device__ __align__(128) unsigned int g_y[N_NODES_MAX * YROW];   // xw*dinv as half2, 64B rows
__device__ __align__(128) float g_emb[N_NODES_MAX * EMBED];       // post-norm/relu embeddings
__device__ __align__(128) unsigned long long g_degpack[N_NODES_MAX]; // cnt<<44 | wsum*2^24
__device__ __align__(128) float g_dinv[N_NODES_MAX];
__device__ __align__(128) int   g_cnt[N_NODES_MAX];
__device__ __align__(128) int   g_start[N_NODES_MAX];
__device__ __align__(128) int   g_fill[N_NODES_MAX];
__device__ __align__(128) int   g_total;
__device__ __align__(128) unsigned long long g_epair[N_EDGES_MAX]; // (w:f32)<<32 | src
__device__ __align__(128) float g_gmax[N_GRAPHS * EMBED];
__device__ __align__(128) float g_gsum[N_GRAPHS * EMBED];
__device__ __align__(128) float g_gcnt[N_GRAPHS];
__device__ int g_ei64;
__device__ int g_batch64;

__device__ __forceinline__ int load_idx(const void* p, size_t i, int is64, int limit) {
    long long v = is64 ? ((const long long*)p)[i] : (long long)((const int*)p)[i];
    int iv = (int)v;
    if (iv < 0) iv = 0;
    if (iv >= limit) iv = limit - 1;
    return iv;
}

// ---------------------------------------------------------------------------
// Probe dtypes (int64 little-endian small values => odd 32-bit words all 0)
// ---------------------------------------------------------------------------
__global__ void k_probe(const unsigned int* ei, const unsigned int* batch, int n) {
    int bad_ei = 0, bad_b = 0;
    for (int i = threadIdx.x; i < 1024; i += 256)
        if (ei[2 * i + 1] != 0u) bad_ei = 1;
    int base = n / 4;
    for (int i = threadIdx.x; i < 1024; i += 256)
        if (batch[2 * (base + i) + 1] != 0u) bad_b = 1;
    int any_ei = __syncthreads_or(bad_ei);
    int any_b  = __syncthreads_or(bad_b);
    if (threadIdx.x == 0) { g_ei64 = any_ei ? 0 : 1; g_batch64 = any_b ? 0 : 1; }
}

// ---------------------------------------------------------------------------
__global__ void k_init(int n) {
    int i = blockIdx.x * blockDim.x + threadIdx.x;
    if (i < n) { g_degpack[i] = 0ull; g_fill[i] = 0; }
    if (i == 0) g_total = 0;
}

// ---------------------------------------------------------------------------
// xw = x @ W  (fp32, one thread per node, W staged in smem)
// ---------------------------------------------------------------------------
__global__ __launch_bounds__(256) void k_xw(const float* __restrict__ x,
                                            const float* __restrict__ W, int n) {
    __shared__ float Ws[N_FEAT * EMBED];
    for (int i = threadIdx.x; i < N_FEAT * EMBED; i += 256) Ws[i] = W[i];
    __syncthreads();
    int node = blockIdx.x * 256 + threadIdx.x;
    if (node >= n) return;
    float acc[EMBED];
#pragma unroll
    for (int j = 0; j < EMBED; j++) acc[j] = 0.0f;
    const float4* xr = (const float4*)(x + (size_t)node * N_FEAT);
#pragma unroll 8
    for (int k4 = 0; k4 < N_FEAT / 4; k4++) {
        float4 v = __ldg(&xr[k4]);
        const float* Wr = &Ws[(k4 * 4) * EMBED];
#pragma unroll
        for (int j = 0; j < EMBED; j++) {
            float a = acc[j];
            a = fmaf(v.x, Wr[j], a);
            a = fmaf(v.y, Wr[EMBED + j], a);
            a = fmaf(v.z, Wr[2 * EMBED + j], a);
            a = fmaf(v.w, Wr[3 * EMBED + j], a);
            acc[j] = a;
        }
    }
    float4* o = (float4*)&g_xw[node * EMBED];
#pragma unroll
    for (int q = 0; q < 5; q++) {
        float4 v;
        v.x = acc[q * 4 + 0]; v.y = acc[q * 4 + 1];
        v.z = acc[q * 4 + 2]; v.w = acc[q * 4 + 3];
        o[q] = v;
    }
}

// ---------------------------------------------------------------------------
// One packed 64-bit atomic per edge: cnt in [44:64), wsum fixed-point 2^24 below
// ---------------------------------------------------------------------------
__global__ void k_deg(const void* __restrict__ ei,
                      const float* __restrict__ w, int E, int n) {
    int e = blockIdx.x * blockDim.x + threadIdx.x;
    if (e >= E) return;
    int d = load_idx(ei, (size_t)E + e, g_ei64, n);
    unsigned long long p = (1ull << 44) |
        (unsigned long long)(unsigned int)__float2uint_rn(w[e] * 16777216.0f);
    atomicAdd(&g_degpack[d], p);
}

// ---------------------------------------------------------------------------
// Unpack deg/cnt; dinv = rsqrt(deg); CSR offsets (warp-scan, 1 atomic/warp);
// build fp16 y-table: y[i] = xw[i] * dinv[i], 64B-aligned rows
// ---------------------------------------------------------------------------
__global__ void k_start(int n) {
    int i = blockIdx.x * blockDim.x + threadIdx.x;
    int lane = threadIdx.x & 31;
    int c = 0;
    float di = 0.0f;
    if (i < n) {
        unsigned long long p = g_degpack[i];
        c = (int)(p >> 44);
        float deg = 1.0f + (float)(p & ((1ull << 44) - 1ull)) * (1.0f / 16777216.0f);
        di = (deg > 0.0f) ? rsqrtf(deg) : 0.0f;
        g_dinv[i] = di;
        g_cnt[i] = c;
    }
    int pre = c;
#pragma unroll
    for (int o = 1; o < 32; o <<= 1) {
        int v = __shfl_up_sync(0xffffffffu, pre, o);
        if (lane >= o) pre += v;
    }
    int warp_tot = __shfl_sync(0xffffffffu, pre, 31);
    int base = 0;
    if (lane == 31) base = atomicAdd(&g_total, warp_tot);
    base = __shfl_sync(0xffffffffu, base, 31);
    if (i < n) {
        g_start[i] = base + (pre - c);
        // fp16 y row
        const float4* p4 = (const float4*)&g_xw[i * EMBED];
        unsigned int* yo = &g_y[i * YROW];
#pragma unroll
        for (int q = 0; q < 5; q++) {
            float4 v = p4[q];
            __half2 h0 = __floats2half2_rn(v.x * di, v.y * di);
            __half2 h1 = __floats2half2_rn(v.z * di, v.w * di);
            yo[q * 2 + 0] = *(unsigned int*)&h0;
            yo[q * 2 + 1] = *(unsigned int*)&h1;
        }
    }
}

// ---------------------------------------------------------------------------
// Bin edges by dst: one packed 8B store (w<<32 | src); no dinv reads
// ---------------------------------------------------------------------------
__global__ void k_scatter(const void* __restrict__ ei,
                          const float* __restrict__ w, int E, int n) {
    int e = blockIdx.x * blockDim.x + threadIdx.x;
    if (e >= E) return;
    int is64 = g_ei64;
    int s = load_idx(ei, e, is64, n);
    int d = load_idx(ei, (size_t)E + e, is64, n);
    int pos = g_start[d] + atomicAdd(&g_fill[d], 1);
    if (pos < 0) pos = 0;
    if (pos >= N_EDGES_MAX) pos = N_EDGES_MAX - 1;
    g_epair[pos] = ((unsigned long long)__float_as_uint(w[e]) << 32) | (unsigned int)s;
}

// ---------------------------------------------------------------------------
// Gather: acc = xw[i]*dinv^2 + sum_edges y_h[s] * (w * dinv[i]);
// fused +b / L2-normalize / ReLU.  Per-edge traffic: 8B CSR + 64B y row.
// ---------------------------------------------------------------------------
__global__ __launch_bounds__(256) void k_gather(const float* __restrict__ b, int n) {
    int i = blockIdx.x * 256 + threadIdx.x;
    if (i >= n) return;
    float di = g_dinv[i];
    float acc[EMBED];
    {
        float s2 = di * di;
        const float4* p = (const float4*)&g_xw[i * EMBED];
#pragma unroll
        for (int q = 0; q < 5; q++) {
            float4 v = p[q];
            acc[q * 4 + 0] = v.x * s2; acc[q * 4 + 1] = v.y * s2;
            acc[q * 4 + 2] = v.z * s2; acc[q * 4 + 3] = v.w * s2;
        }
    }
    int st = g_start[i];
    int c  = g_cnt[i];
    for (int k = 0; k < c; k++) {
        unsigned long long pr = g_epair[st + k];
        int s = (int)(unsigned int)(pr & 0xffffffffull);
        float nm = __uint_as_float((unsigned int)(pr >> 32)) * di;
        const uint4* yr = (const uint4*)&g_y[s * YROW];
        uint4 a0 = __ldg(&yr[0]);           // halfs 0..7
        uint4 a1 = __ldg(&yr[1]);           // halfs 8..15
        uint2 a2 = __ldg((const uint2*)&yr[2]); // halfs 16..19
        const unsigned int hw[10] = {a0.x, a0.y, a0.z, a0.w,
                                     a1.x, a1.y, a1.z, a1.w,
                                     a2.x, a2.y};
#pragma unroll
        for (int q = 0; q < 10; q++) {
            float2 f = __half22float2(*(const __half2*)&hw[q]);
            acc[q * 2 + 0] = fmaf(f.x, nm, acc[q * 2 + 0]);
            acc[q * 2 + 1] = fmaf(f.y, nm, acc[q * 2 + 1]);
        }
    }
    float ss = 0.0f;
#pragma unroll
    for (int j = 0; j < EMBED; j++) {
        acc[j] += b[j];
        ss = fmaf(acc[j], acc[j], ss);
    }
    float inv = 1.0f / fmaxf(sqrtf(ss), 1e-12f);
    float4* o = (float4*)&g_emb[i * EMBED];
#pragma unroll
    for (int q = 0; q < 5; q++) {
        float4 v;
        v.x = fmaxf(acc[q * 4 + 0] * inv, 0.0f);
        v.y = fmaxf(acc[q * 4 + 1] * inv, 0.0f);
        v.z = fmaxf(acc[q * 4 + 2] * inv, 0.0f);
        v.w = fmaxf(acc[q * 4 + 3] * inv, 0.0f);
        o[q] = v;
    }
}

// ---------------------------------------------------------------------------
// Pooling: one block per graph; shfl/shared tree reductions; no atomics
// ---------------------------------------------------------------------------
__device__ __forceinline__ long long load_b(const void* p, int i, int is64) {
    return is64 ? ((const long long*)p)[i] : (long long)((const int*)p)[i];
}

__global__ __launch_bounds__(256) void k_pool(const void* __restrict__ batch, int n) {
    int g = blockIdx.x;
    int is64 = g_batch64;
    int lo = 0, hi = n;
    while (lo < hi) { int m = (lo + hi) >> 1; if (load_b(batch, m, is64) < (long long)g) lo = m + 1; else hi = m; }
    int beg = lo;
    lo = beg; hi = n;
    while (lo < hi) { int m = (lo + hi) >> 1; if (load_b(batch, m, is64) < (long long)(g + 1)) lo = m + 1; else hi = m; }
    int end = lo;

    float mx[EMBED], sm[EMBED];
#pragma unroll
    for (int j = 0; j < EMBED; j++) { mx[j] = 0.0f; sm[j] = 0.0f; }
    int cnt = 0;
    for (int i = beg + threadIdx.x; i < end; i += 256) {
        const float4* p = (const float4*)&g_emb[i * EMBED];
#pragma unroll
        for (int q = 0; q < 5; q++) {
            float4 v = p[q];
            mx[q * 4 + 0] = fmaxf(mx[q * 4 + 0], v.x); sm[q * 4 + 0] += v.x;
            mx[q * 4 + 1] = fmaxf(mx[q * 4 + 1], v.y); sm[q * 4 + 1] += v.y;
            mx[q * 4 + 2] = fmaxf(mx[q * 4 + 2], v.z); sm[q * 4 + 2] += v.z;
            mx[q * 4 + 3] = fmaxf(mx[q * 4 + 3], v.w); sm[q * 4 + 3] += v.w;
        }
        cnt++;
    }
#pragma unroll
    for (int o = 16; o > 0; o >>= 1) {
#pragma unroll
        for (int j = 0; j < EMBED; j++) {
            mx[j] = fmaxf(mx[j], __shfl_down_sync(0xffffffffu, mx[j], o));
            sm[j] += __shfl_down_sync(0xffffffffu, sm[j], o);
        }
        cnt += __shfl_down_sync(0xffffffffu, cnt, o);
    }
    __shared__ float wmx[8][EMBED];
    __shared__ float wsm[8][EMBED];
    __shared__ int   wcnt[8];
    int wid = threadIdx.x >> 5, lane = threadIdx.x & 31;
    if (lane == 0) {
#pragma unroll
        for (int j = 0; j < EMBED; j++) { wmx[wid][j] = mx[j]; wsm[wid][j] = sm[j]; }
        wcnt[wid] = cnt;
    }
    __syncthreads();
    if (threadIdx.x < EMBED) {
        int j = threadIdx.x;
        float m = wmx[0][j], s = wsm[0][j];
#pragma unroll
        for (int wv = 1; wv < 8; wv++) { m = fmaxf(m, wmx[wv][j]); s += wsm[wv][j]; }
        g_gmax[g * EMBED + j] = m;
        g_gsum[g * EMBED + j] = s;
    }
    if (threadIdx.x == 32) {
        int c = wcnt[0];
#pragma unroll
        for (int wv = 1; wv < 8; wv++) c += wcnt[wv];
        g_gcnt[g] = (float)c;
    }
}

// ---------------------------------------------------------------------------
__global__ void k_final(const float* __restrict__ linW,
                        const float* __restrict__ linb, float* __restrict__ out) {
    int t = blockIdx.x * blockDim.x + threadIdx.x;
    if (t >= N_GRAPHS * N_CLASSES) return;
    int g = t / N_CLASSES, c = t % N_CLASSES;
    float inv = 1.0f / fmaxf(g_gcnt[g], 1.0f);
    float acc = linb[c];
#pragma unroll
    for (int k = 0; k < EMBED; k++)
        acc = fmaf(g_gmax[g * EMBED + k], linW[k * N_CLASSES + c], acc);
#pragma unroll
    for (int k = 0; k < EMBED; k++)
        acc = fmaf(g_gsum[g * EMBED + k] * inv, linW[(EMBED + k) * N_CLASSES + c], acc);
    out[g * N_CLASSES + c] = acc;
}

// ---------------------------------------------------------------------------
extern "C" void kernel_launch(void* const* d_in, const int* in_sizes, int n_in,
                              void* d_out, int out_size) {
    const float* x = 0; const void* ei = 0; const float* w = 0; const void* batch = 0;
    const float* W = 0; const float* b = 0; const float* linW = 0; const float* linb = 0;
    for (int i = 0; i < n_in; i++) {
        switch (in_sizes[i]) {
            case 12800000: x     = (const float*)d_in[i]; break;
            case 6400000:  ei    = d_in[i];               break;
            case 3200000:  w     = (const float*)d_in[i]; break;
            case 100000:   batch = d_in[i];               break;
            case 2560:     W     = (const float*)d_in[i]; break;
            case 400:      linW  = (const float*)d_in[i]; break;
            case 20:       b     = (const float*)d_in[i]; break;
            case 10:       linb  = (const float*)d_in[i]; break;
            default: break;
        }
    }
    if (!x || !ei || !w || !batch || !W || !b || !linW || !linb) {
        x = (const float*)d_in[0]; ei = d_in[1]; w = (const float*)d_in[2];
        batch = d_in[3]; W = (const float*)d_in[4]; b = (const float*)d_in[5];
        linW = (const float*)d_in[6]; linb = (const float*)d_in[7];
    }
    int n = 100000, E = 3200000;
    for (int i = 0; i < n_in; i++) {
        if (d_in[i] == (const void*)batch) n = in_sizes[i];
        if (d_in[i] == ei) E = in_sizes[i] / 2;
    }

    k_probe<<<1, 256>>>((const unsigned int*)ei, (const unsigned int*)batch, n);
    k_init<<<(n + 255) / 256, 256>>>(n);
    k_xw<<<(n + 255) / 256, 256>>>(x, W, n);
    k_deg<<<(E + 255) / 256, 256>>>(ei, w, E, n);
    k_start<<<(n + 255) / 256, 256>>>(n);
    k_scatter<<<(E + 255) / 256, 256>>>(ei, w, E, n);
    k_gather<<<(n + 255) / 256, 256>>>(b, n);
    k_pool<<<N_GRAPHS, 256>>>(batch, n);
    k_final<<<(N_GRAPHS * N_CLASSES + 255) / 256, 256>>>(linW, linb, (float*)d_out);
}

// round 9
// speedup vs baseline: 1.4096x; 1.0522x over previous
#include <cuda_runtime.h>
#include <cuda_fp16.h>

#define N_NODES_MAX 100096
#define N_EDGES_MAX 3200256
#define N_FEAT 128
#define EMBED 20
#define N_GRAPHS 64
#define N_CLASSES 10
#define YROW 16  // uints per y-row (64B: 20 halfs used, padded to 32)

// Scratch (device globals; no dynamic allocation allowed)
__device__ __align__(128) float g_xw[N_NODES_MAX * EMBED];        // x @ W (fp32, self term)
__device__ __align__(128) unsigned int g_y[N_NODES_MAX * YROW];   // xw*dinv as half2, 64B rows
__device__ __align__(128) float g_emb[N_NODES_MAX * EMBED];       // post-norm/relu embeddings
__device__ __align__(128) unsigned long long g_degpack[N_NODES_MAX]; // cnt<<44 | wsum*2^24
__device__ __align__(128) float g_dinv[N_NODES_MAX];
__device__ __align__(128) int   g_cnt[N_NODES_MAX];
__device__ __align__(128) int   g_start[N_NODES_MAX];
__device__ __align__(128) int   g_fill[N_NODES_MAX];
__device__ __align__(128) int   g_total;
__device__ __align__(128) unsigned long long g_epair[N_EDGES_MAX]; // (w:f32)<<32 | src
__device__ __align__(128) float g_gmax[N_GRAPHS * EMBED];
__device__ __align__(128) float g_gsum[N_GRAPHS * EMBED];
__device__ __align__(128) float g_gcnt[N_GRAPHS];
__device__ int g_ei64;
__device__ int g_batch64;

__device__ __forceinline__ int load_idx(const void* p, size_t i, int is64, int limit) {
    long long v = is64 ? ((const long long*)p)[i] : (long long)((const int*)p)[i];
    int iv = (int)v;
    if (iv < 0) iv = 0;
    if (iv >= limit) iv = limit - 1;
    return iv;
}

// ---------------------------------------------------------------------------
// Init + dtype probe (block 0 probes; int64 small values => odd words all 0)
// ---------------------------------------------------------------------------
__global__ void k_init(const unsigned int* ei, const unsigned int* batch, int n) {
    int i = blockIdx.x * blockDim.x + threadIdx.x;
    if (i < n) { g_degpack[i] = 0ull; g_fill[i] = 0; }
    if (i == 0) g_total = 0;
    if (blockIdx.x == 0) {
        int bad_ei = 0, bad_b = 0;
        for (int k = threadIdx.x; k < 1024; k += blockDim.x)
            if (ei[2 * k + 1] != 0u) bad_ei = 1;
        int base = n / 4;
        for (int k = threadIdx.x; k < 1024; k += blockDim.x)
            if (batch[2 * (base + k) + 1] != 0u) bad_b = 1;
        int any_ei = __syncthreads_or(bad_ei);
        int any_b  = __syncthreads_or(bad_b);
        if (threadIdx.x == 0) { g_ei64 = any_ei ? 0 : 1; g_batch64 = any_b ? 0 : 1; }
    }
}

// ---------------------------------------------------------------------------
// Fused: blocks [0, nbx) compute xw = x @ W (FMA/LDS-bound);
//        blocks [nbx, nbx+nbe) do packed deg atomics (L2-atomic-bound).
// The two phases use different pipes and overlap across SMs.
// ---------------------------------------------------------------------------
__global__ __launch_bounds__(256) void k_xw_deg(const float* __restrict__ x,
                                                const float* __restrict__ W,
                                                const void* __restrict__ ei,
                                                const float* __restrict__ w,
                                                int n, int E, int nbx) {
    if (blockIdx.x >= (unsigned)nbx) {
        int e = (blockIdx.x - nbx) * 256 + threadIdx.x;
        if (e >= E) return;
        int d = load_idx(ei, (size_t)E + e, g_ei64, n);
        unsigned long long p = (1ull << 44) |
            (unsigned long long)(unsigned int)__float2uint_rn(w[e] * 16777216.0f);
        atomicAdd(&g_degpack[d], p);
        return;
    }
    __shared__ float Ws[N_FEAT * EMBED];
    for (int i = threadIdx.x; i < N_FEAT * EMBED; i += 256) Ws[i] = W[i];
    __syncthreads();
    int node = blockIdx.x * 256 + threadIdx.x;
    if (node >= n) return;
    float acc[EMBED];
#pragma unroll
    for (int j = 0; j < EMBED; j++) acc[j] = 0.0f;
    const float4* xr = (const float4*)(x + (size_t)node * N_FEAT);
#pragma unroll 8
    for (int k4 = 0; k4 < N_FEAT / 4; k4++) {
        float4 v = __ldg(&xr[k4]);
        const float* Wr = &Ws[(k4 * 4) * EMBED];
#pragma unroll
        for (int j = 0; j < EMBED; j++) {
            float a = acc[j];
            a = fmaf(v.x, Wr[j], a);
            a = fmaf(v.y, Wr[EMBED + j], a);
            a = fmaf(v.z, Wr[2 * EMBED + j], a);
            a = fmaf(v.w, Wr[3 * EMBED + j], a);
            acc[j] = a;
        }
    }
    float4* o = (float4*)&g_xw[node * EMBED];
#pragma unroll
    for (int q = 0; q < 5; q++) {
        float4 v;
        v.x = acc[q * 4 + 0]; v.y = acc[q * 4 + 1];
        v.z = acc[q * 4 + 2]; v.w = acc[q * 4 + 3];
        o[q] = v;
    }
}

// ---------------------------------------------------------------------------
// Unpack deg/cnt; dinv = rsqrt(deg); CSR offsets (warp-scan, 1 atomic/warp);
// build fp16 y-table: y[i] = xw[i] * dinv[i], 64B-aligned rows
// ---------------------------------------------------------------------------
__global__ void k_start(int n) {
    int i = blockIdx.x * blockDim.x + threadIdx.x;
    int lane = threadIdx.x & 31;
    int c = 0;
    float di = 0.0f;
    if (i < n) {
        unsigned long long p = g_degpack[i];
        c = (int)(p >> 44);
        float deg = 1.0f + (float)(p & ((1ull << 44) - 1ull)) * (1.0f / 16777216.0f);
        di = (deg > 0.0f) ? rsqrtf(deg) : 0.0f;
        g_dinv[i] = di;
        g_cnt[i] = c;
    }
    int pre = c;
#pragma unroll
    for (int o = 1; o < 32; o <<= 1) {
        int v = __shfl_up_sync(0xffffffffu, pre, o);
        if (lane >= o) pre += v;
    }
    int warp_tot = __shfl_sync(0xffffffffu, pre, 31);
    int base = 0;
    if (lane == 31) base = atomicAdd(&g_total, warp_tot);
    base = __shfl_sync(0xffffffffu, base, 31);
    if (i < n) {
        g_start[i] = base + (pre - c);
        const float4* p4 = (const float4*)&g_xw[i * EMBED];
        unsigned int* yo = &g_y[i * YROW];
#pragma unroll
        for (int q = 0; q < 5; q++) {
            float4 v = p4[q];
            __half2 h0 = __floats2half2_rn(v.x * di, v.y * di);
            __half2 h1 = __floats2half2_rn(v.z * di, v.w * di);
            yo[q * 2 + 0] = *(unsigned int*)&h0;
            yo[q * 2 + 1] = *(unsigned int*)&h1;
        }
    }
}

// ---------------------------------------------------------------------------
// Bin edges by dst: one packed 8B store (w<<32 | src)
// ---------------------------------------------------------------------------
__global__ void k_scatter(const void* __restrict__ ei,
                          const float* __restrict__ w, int E, int n) {
    int e = blockIdx.x * blockDim.x + threadIdx.x;
    if (e >= E) return;
    int is64 = g_ei64;
    int s = load_idx(ei, e, is64, n);
    int d = load_idx(ei, (size_t)E + e, is64, n);
    int pos = g_start[d] + atomicAdd(&g_fill[d], 1);
    if (pos < 0) pos = 0;
    if (pos >= N_EDGES_MAX) pos = N_EDGES_MAX - 1;
    g_epair[pos] = ((unsigned long long)__float_as_uint(w[e]) << 32) | (unsigned int)s;
}

// ---------------------------------------------------------------------------
// Gather, 4x unrolled for MLP: batch 4 epair loads, then 12 y-row loads,
// then FMAs. Fused +b / L2-normalize / ReLU.
// ---------------------------------------------------------------------------
__device__ __forceinline__ void gy_load(int s, unsigned int hw[10]) {
    const uint4* yr = (const uint4*)&g_y[s * YROW];
    uint4 a0 = __ldg(&yr[0]);
    uint4 a1 = __ldg(&yr[1]);
    uint2 a2 = __ldg((const uint2*)&yr[2]);
    hw[0] = a0.x; hw[1] = a0.y; hw[2] = a0.z; hw[3] = a0.w;
    hw[4] = a1.x; hw[5] = a1.y; hw[6] = a1.z; hw[7] = a1.w;
    hw[8] = a2.x; hw[9] = a2.y;
}

__device__ __forceinline__ void gy_fma(const unsigned int hw[10], float nm, float acc[EMBED]) {
#pragma unroll
    for (int q = 0; q < 10; q++) {
        float2 f = __half22float2(*(const __half2*)&hw[q]);
        acc[q * 2 + 0] = fmaf(f.x, nm, acc[q * 2 + 0]);
        acc[q * 2 + 1] = fmaf(f.y, nm, acc[q * 2 + 1]);
    }
}

__global__ __launch_bounds__(256) void k_gather(const float* __restrict__ b, int n) {
    int i = blockIdx.x * 256 + threadIdx.x;
    if (i >= n) return;
    float di = g_dinv[i];
    float acc[EMBED];
    {
        float s2 = di * di;
        const float4* p = (const float4*)&g_xw[i * EMBED];
#pragma unroll
        for (int q = 0; q < 5; q++) {
            float4 v = p[q];
            acc[q * 4 + 0] = v.x * s2; acc[q * 4 + 1] = v.y * s2;
            acc[q * 4 + 2] = v.z * s2; acc[q * 4 + 3] = v.w * s2;
        }
    }
    int st = g_start[i];
    int c  = g_cnt[i];
    int k = 0;
    for (; k + 4 <= c; k += 4) {
        unsigned long long p0 = __ldg(&g_epair[st + k + 0]);
        unsigned long long p1 = __ldg(&g_epair[st + k + 1]);
        unsigned long long p2 = __ldg(&g_epair[st + k + 2]);
        unsigned long long p3 = __ldg(&g_epair[st + k + 3]);
        int s0 = (int)(unsigned int)p0, s1 = (int)(unsigned int)p1;
        int s2i = (int)(unsigned int)p2, s3 = (int)(unsigned int)p3;
        float n0 = __uint_as_float((unsigned int)(p0 >> 32)) * di;
        float n1 = __uint_as_float((unsigned int)(p1 >> 32)) * di;
        float n2 = __uint_as_float((unsigned int)(p2 >> 32)) * di;
        float n3 = __uint_as_float((unsigned int)(p3 >> 32)) * di;
        unsigned int h0[10], h1[10], h2[10], h3[10];
        gy_load(s0, h0); gy_load(s1, h1); gy_load(s2i, h2); gy_load(s3, h3);
        gy_fma(h0, n0, acc); gy_fma(h1, n1, acc);
        gy_fma(h2, n2, acc); gy_fma(h3, n3, acc);
    }
    for (; k < c; k++) {
        unsigned long long pr = __ldg(&g_epair[st + k]);
        int s = (int)(unsigned int)pr;
        float nm = __uint_as_float((unsigned int)(pr >> 32)) * di;
        unsigned int hw[10];
        gy_load(s, hw);
        gy_fma(hw, nm, acc);
    }
    float ss = 0.0f;
#pragma unroll
    for (int j = 0; j < EMBED; j++) {
        acc[j] += b[j];
        ss = fmaf(acc[j], acc[j], ss);
    }
    float inv = 1.0f / fmaxf(sqrtf(ss), 1e-12f);
    float4* o = (float4*)&g_emb[i * EMBED];
#pragma unroll
    for (int q = 0; q < 5; q++) {
        float4 v;
        v.x = fmaxf(acc[q * 4 + 0] * inv, 0.0f);
        v.y = fmaxf(acc[q * 4 + 1] * inv, 0.0f);
        v.z = fmaxf(acc[q * 4 + 2] * inv, 0.0f);
        v.w = fmaxf(acc[q * 4 + 3] * inv, 0.0f);
        o[q] = v;
    }
}

// ---------------------------------------------------------------------------
// Pooling: one block per graph; shfl/shared tree reductions; no atomics
// ---------------------------------------------------------------------------
__device__ __forceinline__ long long load_b(const void* p, int i, int is64) {
    return is64 ? ((const long long*)p)[i] : (long long)((const int*)p)[i];
}

__global__ __launch_bounds__(256) void k_pool(const void* __restrict__ batch, int n) {
    int g = blockIdx.x;
    int is64 = g_batch64;
    int lo = 0, hi = n;
    while (lo < hi) { int m = (lo + hi) >> 1; if (load_b(batch, m, is64) < (long long)g) lo = m + 1; else hi = m; }
    int beg = lo;
    lo = beg; hi = n;
    while (lo < hi) { int m = (lo + hi) >> 1; if (load_b(batch, m, is64) < (long long)(g + 1)) lo = m + 1; else hi = m; }
    int end = lo;

    float mx[EMBED], sm[EMBED];
#pragma unroll
    for (int j = 0; j < EMBED; j++) { mx[j] = 0.0f; sm[j] = 0.0f; }
    int cnt = 0;
    for (int i = beg + threadIdx.x; i < end; i += 256) {
        const float4* p = (const float4*)&g_emb[i * EMBED];
#pragma unroll
        for (int q = 0; q < 5; q++) {
            float4 v = p[q];
            mx[q * 4 + 0] = fmaxf(mx[q * 4 + 0], v.x); sm[q * 4 + 0] += v.x;
            mx[q * 4 + 1] = fmaxf(mx[q * 4 + 1], v.y); sm[q * 4 + 1] += v.y;
            mx[q * 4 + 2] = fmaxf(mx[q * 4 + 2], v.z); sm[q * 4 + 2] += v.z;
            mx[q * 4 + 3] = fmaxf(mx[q * 4 + 3], v.w); sm[q * 4 + 3] += v.w;
        }
        cnt++;
    }
#pragma unroll
    for (int o = 16; o > 0; o >>= 1) {
#pragma unroll
        for (int j = 0; j < EMBED; j++) {
            mx[j] = fmaxf(mx[j], __shfl_down_sync(0xffffffffu, mx[j], o));
            sm[j] += __shfl_down_sync(0xffffffffu, sm[j], o);
        }
        cnt += __shfl_down_sync(0xffffffffu, cnt, o);
    }
    __shared__ float wmx[8][EMBED];
    __shared__ float wsm[8][EMBED];
    __shared__ int   wcnt[8];
    int wid = threadIdx.x >> 5, lane = threadIdx.x & 31;
    if (lane == 0) {
#pragma unroll
        for (int j = 0; j < EMBED; j++) { wmx[wid][j] = mx[j]; wsm[wid][j] = sm[j]; }
        wcnt[wid] = cnt;
    }
    __syncthreads();
    if (threadIdx.x < EMBED) {
        int j = threadIdx.x;
        float m = wmx[0][j], s = wsm[0][j];
#pragma unroll
        for (int wv = 1; wv < 8; wv++) { m = fmaxf(m, wmx[wv][j]); s += wsm[wv][j]; }
        g_gmax[g * EMBED + j] = m;
        g_gsum[g * EMBED + j] = s;
    }
    if (threadIdx.x == 32) {
        int c = wcnt[0];
#pragma unroll
        for (int wv = 1; wv < 8; wv++) c += wcnt[wv];
        g_gcnt[g] = (float)c;
    }
}

// ---------------------------------------------------------------------------
__global__ void k_final(const float* __restrict__ linW,
                        const float* __restrict__ linb, float* __restrict__ out) {
    int t = blockIdx.x * blockDim.x + threadIdx.x;
    if (t >= N_GRAPHS * N_CLASSES) return;
    int g = t / N_CLASSES, c = t % N_CLASSES;
    float inv = 1.0f / fmaxf(g_gcnt[g], 1.0f);
    float acc = linb[c];
#pragma unroll
    for (int k = 0; k < EMBED; k++)
        acc = fmaf(g_gmax[g * EMBED + k], linW[k * N_CLASSES + c], acc);
#pragma unroll
    for (int k = 0; k < EMBED; k++)
        acc = fmaf(g_gsum[g * EMBED + k] * inv, linW[(EMBED + k) * N_CLASSES + c], acc);
    out[g * N_CLASSES + c] = acc;
}

// ---------------------------------------------------------------------------
extern "C" void kernel_launch(void* const* d_in, const int* in_sizes, int n_in,
                              void* d_out, int out_size) {
    const float* x = 0; const void* ei = 0; const float* w = 0; const void* batch = 0;
    const float* W = 0; const float* b = 0; const float* linW = 0; const float* linb = 0;
    for (int i = 0; i < n_in; i++) {
        switch (in_sizes[i]) {
            case 12800000: x     = (const float*)d_in[i]; break;
            case 6400000:  ei    = d_in[i];               break;
            case 3200000:  w     = (const float*)d_in[i]; break;
            case 100000:   batch = d_in[i];               break;
            case 2560:     W     = (const float*)d_in[i]; break;
            case 400:      linW  = (const float*)d_in[i]; break;
            case 20:       b     = (const float*)d_in[i]; break;
            case 10:       linb  = (const float*)d_in[i]; break;
            default: break;
        }
    }
    if (!x || !ei || !w || !batch || !W || !b || !linW || !linb) {
        x = (const float*)d_in[0]; ei = d_in[1]; w = (const float*)d_in[2];
        batch = d_in[3]; W = (const float*)d_in[4]; b = (const float*)d_in[5];
        linW = (const float*)d_in[6]; linb = (const float*)d_in[7];
    }
    int n = 100000, E = 3200000;
    for (int i = 0; i < n_in; i++) {
        if (d_in[i] == (const void*)batch) n = in_sizes[i];
        if (d_in[i] == ei) E = in_sizes[i] / 2;
    }
    int nbx = (n + 255) / 256;
    int nbe = (E + 255) / 256;

    k_init<<<nbx, 256>>>((const unsigned int*)ei, (const unsigned int*)batch, n);
    k_xw_deg<<<nbx + nbe, 256>>>(x, W, ei, w, n, E, nbx);
    k_start<<<nbx, 256>>>(n);
    k_scatter<<<nbe, 256>>>(ei, w, E, n);
    k_gather<<<nbx, 256>>>(b, n);
    k_pool<<<N_GRAPHS, 256>>>(batch, n);
    k_final<<<(N_GRAPHS * N_CLASSES + 255) / 256, 256>>>(linW, linb, (float*)d_out);
}